// round 2
// baseline (speedup 1.0000x reference)
#include <cuda_runtime.h>

// Problem constants
#define BB    4
#define LL    1024
#define DIMD  512
#define HH    8
#define BL    (BB*LL)          // 4096

__device__ __forceinline__ float sqrt_approx(float x){ float y; asm("sqrt.approx.f32 %0, %1;" : "=f"(y) : "f"(x)); return y; }
__device__ __forceinline__ float ex2_approx (float x){ float y; asm("ex2.approx.f32 %0, %1;"  : "=f"(y) : "f"(x)); return y; }

// -------- scratch (static device memory; no allocation) --------
__device__ float  g_Rt [BL*12];          // R row-major (9) + t (3) per (b,l)
__device__ float4 g_QR [BB*HH*LL];       // rotated qr
__device__ float4 g_QD [BB*HH*LL];       // rotated qd (+t)
__device__ float4 g_KEY[BB*HH*LL*3];     // per key j: {kr_g}, {kd_g(+t) or 1e18 if masked}, {v_g}
__device__ float4 g_OG [BL*HH];          // attention output in global frame

// ================= kernel 1: frames =================
__global__ void k_frames(const float* __restrict__ coords,
                         const int* __restrict__ cmask)
{
    int idx = blockIdx.x * blockDim.x + threadIdx.x;
    if (idx >= BL) return;
    const float* cp = coords + idx * 9;
    float nx=cp[0], ny=cp[1], nz=cp[2];
    float cax=cp[3], cay=cp[4], caz=cp[5];
    float cx=cp[6], cy=cp[7], cz=cp[8];

    // x_axis = normalize(ca - c)
    float xx=cax-cx, xy=cay-cy, xz=caz-cz;
    float inv = 1.f / fmaxf(sqrtf(xx*xx + xy*xy + xz*xz), 1e-8f);
    xx*=inv; xy*=inv; xz*=inv;
    // y_axis = normalize( (n-ca) - proj_x(n-ca) )
    float yx=nx-cax, yy=ny-cay, yz=nz-caz;
    float d = xx*yx + xy*yy + xz*yz;
    yx -= d*xx; yy -= d*xy; yz -= d*xz;
    inv = 1.f / fmaxf(sqrtf(yx*yx + yy*yy + yz*yz), 1e-8f);
    yx*=inv; yy*=inv; yz*=inv;
    // z_axis = normalize(cross(x,y))
    float zx = xy*yz - xz*yy;
    float zy = xz*yx - xx*yz;
    float zz = xx*yy - xy*yx;
    inv = 1.f / fmaxf(sqrtf(zx*zx + zy*zy + zz*zz), 1e-8f);
    zx*=inv; zy*=inv; zz*=inv;

    float R[12];
    if (cmask[idx] != 0) {
        R[0]=xx; R[1]=xy; R[2]=xz;
        R[3]=yx; R[4]=yy; R[5]=yz;
        R[6]=zx; R[7]=zy; R[8]=zz;
        R[9]=cax; R[10]=cay; R[11]=caz;
    } else {
        R[0]=1.f; R[1]=0.f; R[2]=0.f;
        R[3]=0.f; R[4]=1.f; R[5]=0.f;
        R[6]=0.f; R[7]=0.f; R[8]=1.f;
        R[9]=0.f; R[10]=0.f; R[11]=0.f;
    }
    #pragma unroll
    for (int i=0;i<12;i++) g_Rt[idx*12+i] = R[i];
}

// ================= kernel 2: fused projections + rotation =================
// block: 128 threads, 16 rows of x; grid 256
__global__ void __launch_bounds__(128) k_proj(
    const float* __restrict__ x,
    const float* __restrict__ W0, const float* __restrict__ b0,
    const float* __restrict__ W1, const float* __restrict__ b1,
    const float* __restrict__ W2, const float* __restrict__ b2,
    const float* __restrict__ W3, const float* __restrict__ b3,
    const float* __restrict__ W4, const float* __restrict__ b4,
    const int* __restrict__ mask)
{
    __shared__ float xs[16*512];     // 32 KB
    __shared__ float sres[16*120];   // 7.5 KB
    int tid  = threadIdx.x;
    int row0 = blockIdx.x * 16;

    // load 16 rows of x (32 KB) with float4
    {
        const float4* src = (const float4*)(x + row0*512);
        float4* dst = (float4*)xs;
        #pragma unroll
        for (int i=0;i<16;i++) dst[tid + i*128] = src[tid + i*128];
    }
    __syncthreads();

    if (tid < 120) {
        int m = tid / 24, c = tid % 24;
        const float* W; const float* bv;
        switch (m) {
            case 0:  W=W0; bv=b0; break;
            case 1:  W=W1; bv=b1; break;
            case 2:  W=W2; bv=b2; break;
            case 3:  W=W3; bv=b3; break;
            default: W=W4; bv=b4; break;
        }
        float bias = bv[c];
        float acc[16];
        #pragma unroll
        for (int r=0;r<16;r++) acc[r] = bias;
        const float* Wc = W + c;
        #pragma unroll 2
        for (int d0=0; d0<512; d0+=4) {
            float w0 = __ldg(Wc + (d0+0)*24);
            float w1 = __ldg(Wc + (d0+1)*24);
            float w2 = __ldg(Wc + (d0+2)*24);
            float w3 = __ldg(Wc + (d0+3)*24);
            #pragma unroll
            for (int r=0;r<16;r++) {
                float4 xv = *(const float4*)&xs[r*512 + d0];
                acc[r] = fmaf(xv.x, w0, fmaf(xv.y, w1, fmaf(xv.z, w2, fmaf(xv.w, w3, acc[r]))));
            }
        }
        #pragma unroll
        for (int r=0;r<16;r++) sres[r*120 + tid] = acc[r];
    }
    __syncthreads();

    // rotation stage: 128 threads = 16 rows x 8 heads
    {
        int r = tid >> 3, h = tid & 7;
        int gl = row0 + r;
        float Rm[12];
        #pragma unroll
        for (int i=0;i<12;i++) Rm[i] = g_Rt[gl*12 + i];
        const float* rowv = &sres[r*120];
        int base = h*3;

        float qr0=rowv[ 0+base], qr1=rowv[ 1+base], qr2=rowv[ 2+base];
        float kr0=rowv[24+base], kr1=rowv[25+base], kr2=rowv[26+base];
        float qd0=rowv[48+base], qd1=rowv[49+base], qd2=rowv[50+base];
        float kd0=rowv[72+base], kd1=rowv[73+base], kd2=rowv[74+base];
        float vv0=rowv[96+base], vv1=rowv[97+base], vv2=rowv[98+base];

        #define ROT3(o0,o1,o2,a0,a1,a2)                          \
            o0 = a0*Rm[0] + a1*Rm[3] + a2*Rm[6];                 \
            o1 = a0*Rm[1] + a1*Rm[4] + a2*Rm[7];                 \
            o2 = a0*Rm[2] + a1*Rm[5] + a2*Rm[8];

        float qrg0,qrg1,qrg2, krg0,krg1,krg2, qdg0,qdg1,qdg2, kdg0,kdg1,kdg2, vg0,vg1,vg2;
        ROT3(qrg0,qrg1,qrg2, qr0,qr1,qr2);
        ROT3(krg0,krg1,krg2, kr0,kr1,kr2);
        ROT3(qdg0,qdg1,qdg2, qd0,qd1,qd2);
        ROT3(kdg0,kdg1,kdg2, kd0,kd1,kd2);
        ROT3(vg0, vg1, vg2,  vv0,vv1,vv2);
        #undef ROT3

        qdg0 += Rm[9]; qdg1 += Rm[10]; qdg2 += Rm[11];
        kdg0 += Rm[9]; kdg1 += Rm[10]; kdg2 += Rm[11];

        if (mask[gl] == 0) {    // masked key: infinite distance -> attn weight 0
            kdg0 = 1e18f; kdg1 = 1e18f; kdg2 = 1e18f;
        }

        int b = gl >> 10, l = gl & 1023;
        int q = ((b*HH + h) << 10) | l;
        g_QR[q] = make_float4(qrg0, qrg1, qrg2, 0.f);
        g_QD[q] = make_float4(qdg0, qdg1, qdg2, 0.f);
        g_KEY[q*3 + 0] = make_float4(krg0, krg1, krg2, 0.f);
        g_KEY[q*3 + 1] = make_float4(kdg0, kdg1, kdg2, 0.f);
        g_KEY[q*3 + 2] = make_float4(vg0,  vg1,  vg2,  0.f);
    }
}

// ================= kernel 3: attention =================
// grid 256 = (b*H + h)*8 + tile ; 128 threads = 128 queries; all 1024 keys in smem
__global__ void __launch_bounds__(128) k_attn(const float* __restrict__ w_r,
                                              const float* __restrict__ w_d)
{
    extern __shared__ float4 skey[];   // 3072 float4 = 48 KB
    int tid  = threadIdx.x;
    int tile = blockIdx.x & 7;
    int bh   = blockIdx.x >> 3;
    int h    = bh & 7;
    int b    = bh >> 3;

    const float4* gk = g_KEY + (size_t)bh * LL * 3;
    #pragma unroll
    for (int i=0;i<24;i++) skey[tid + i*128] = gk[tid + i*128];
    __syncthreads();

    int i = (tile << 7) + tid;
    int q = (bh << 10) + i;
    float4 QR = g_QR[q];
    float4 QD = g_QD[q];

    const float C = 1.44269504088896f * 0.57735026918962f;  // log2(e)/sqrt(3)
    float xr = w_r[h], xd = w_d[h];
    float wr2 = log1pf(__expf(xr)) * C;        // softplus folded with log2e/sqrt3
    float wd2 = log1pf(__expf(xd)) * C;

    float sum = 0.f, a0 = 0.f, a1 = 0.f, a2 = 0.f;
    #pragma unroll 4
    for (int j=0; j<LL; j++) {
        float4 F0 = skey[j*3 + 0];
        float4 F1 = skey[j*3 + 1];
        float4 F2 = skey[j*3 + 2];
        float dir = fmaf(QR.x, F0.x, fmaf(QR.y, F0.y, QR.z * F0.z));
        float dx = QD.x - F1.x;
        float dy = QD.y - F1.y;
        float dz = QD.z - F1.z;
        float d2 = fmaf(dx, dx, fmaf(dy, dy, dz*dz));
        float dist = sqrt_approx(d2);
        float s = fmaf(dir, wr2, -dist * wd2);  // log2-domain score
        float p = ex2_approx(s);
        sum += p;
        a0 = fmaf(p, F2.x, a0);
        a1 = fmaf(p, F2.y, a1);
        a2 = fmaf(p, F2.z, a2);
    }
    float inv = 1.0f / sum;
    g_OG[((b << 10) + i) * HH + h] = make_float4(a0*inv, a1*inv, a2*inv, 0.f);
}

// ================= kernel 4: back-rotation + output projection =================
// block: 256 threads, 32 rows; grid 128
__global__ void __launch_bounds__(256) k_out(
    const float* __restrict__ Wp, const float* __restrict__ bp,
    const int* __restrict__ mask, float* __restrict__ out)
{
    __shared__ float so[32*24];
    __shared__ float smask[32];
    int tid = threadIdx.x;
    int gl0 = blockIdx.x * 32;

    // stage A: o_local = og @ R  (32 rows x 8 heads = 256 workers)
    {
        int r = tid >> 3, h = tid & 7;
        int gl = gl0 + r;
        float4 og = g_OG[gl*HH + h];
        float Rm[9];
        #pragma unroll
        for (int i=0;i<9;i++) Rm[i] = g_Rt[gl*12 + i];
        so[r*24 + h*3 + 0] = og.x*Rm[0] + og.y*Rm[3] + og.z*Rm[6];
        so[r*24 + h*3 + 1] = og.x*Rm[1] + og.y*Rm[4] + og.z*Rm[7];
        so[r*24 + h*3 + 2] = og.x*Rm[2] + og.y*Rm[5] + og.z*Rm[8];
        if (h == 0) smask[r] = (mask[gl] != 0) ? 1.f : 0.f;
    }
    __syncthreads();

    // stage B: out[32 rows][512] = so @ Wp + bp, W_proj column-pair in regs
    int c0 = tid * 2;
    float2 wp[24];
    #pragma unroll
    for (int f=0; f<24; f++) wp[f] = *(const float2*)(Wp + f*512 + c0);
    float2 bb = *(const float2*)(bp + c0);

    for (int r=0; r<32; r++) {
        float acc0 = bb.x, acc1 = bb.y;
        const float* o = &so[r*24];
        #pragma unroll
        for (int f=0; f<24; f++) {
            float ov = o[f];
            acc0 = fmaf(ov, wp[f].x, acc0);
            acc1 = fmaf(ov, wp[f].y, acc1);
        }
        float mf = smask[r];
        int gl = gl0 + r;
        *(float2*)(out + (size_t)gl*512 + c0) = make_float2(acc0*mf, acc1*mf);
    }
}

// ================= launch =================
extern "C" void kernel_launch(void* const* d_in, const int* in_sizes, int n_in,
                              void* d_out, int out_size)
{
    const float* x      = (const float*)d_in[0];
    const float* coords = (const float*)d_in[1];
    const int* cel  = (const int*)d_in[2];
    const int* mask = (const int*)d_in[3];
    const float* Wqr = (const float*)d_in[4];  const float* bqr = (const float*)d_in[5];
    const float* Wkr = (const float*)d_in[6];  const float* bkr = (const float*)d_in[7];
    const float* Wqd = (const float*)d_in[8];  const float* bqd = (const float*)d_in[9];
    const float* Wkd = (const float*)d_in[10]; const float* bkd = (const float*)d_in[11];
    const float* Wv  = (const float*)d_in[12]; const float* bv  = (const float*)d_in[13];
    const float* w_r = (const float*)d_in[14]; const float* w_d = (const float*)d_in[15];
    const float* Wp  = (const float*)d_in[16]; const float* bp  = (const float*)d_in[17];

    k_frames<<<BL/256, 256>>>(coords, cel);
    k_proj  <<<BL/16, 128>>>(x, Wqr,bqr, Wkr,bkr, Wqd,bqd, Wkd,bkd, Wv,bv, mask);
    k_attn  <<<BB*HH*(LL/128), 128, 48*1024>>>(w_r, w_d);
    k_out   <<<BL/32, 256>>>(Wp, bp, mask, (float*)d_out);
}

// round 3
// speedup vs baseline: 1.2353x; 1.2353x over previous
#include <cuda_runtime.h>

#define BB 4
#define LL 1024
#define HH 8
#define BL (BB*LL)        // 4096
#define NBH (BB*HH)       // 32

typedef unsigned long long u64;

__device__ __forceinline__ float sqrt_approx(float x){ float y; asm("sqrt.approx.f32 %0, %1;" : "=f"(y) : "f"(x)); return y; }
__device__ __forceinline__ float ex2_approx (float x){ float y; asm("ex2.approx.f32 %0, %1;"  : "=f"(y) : "f"(x)); return y; }
__device__ __forceinline__ u64 pack2(float lo, float hi){ u64 r; asm("mov.b64 %0, {%1,%2};" : "=l"(r) : "f"(lo), "f"(hi)); return r; }
__device__ __forceinline__ float2 unpack2(u64 v){ float2 f; asm("mov.b64 {%0,%1}, %2;" : "=f"(f.x), "=f"(f.y) : "l"(v)); return f; }
__device__ __forceinline__ u64 fma2(u64 a, u64 b, u64 c){ u64 d; asm("fma.rn.f32x2 %0, %1, %2, %3;" : "=l"(d) : "l"(a), "l"(b), "l"(c)); return d; }
__device__ __forceinline__ u64 mul2(u64 a, u64 b){ u64 d; asm("mul.rn.f32x2 %0, %1, %2;" : "=l"(d) : "l"(a), "l"(b)); return d; }
__device__ __forceinline__ u64 add2(u64 a, u64 b){ u64 d; asm("add.rn.f32x2 %0, %1, %2;" : "=l"(d) : "l"(a), "l"(b)); return d; }

// -------- static scratch --------
__device__ float  g_Rt  [BL*12];            // R (9) + t (3) per (b,l)
__device__ float4 g_QR  [NBH*LL];           // qr_g * wr2
__device__ float4 g_QD  [NBH*LL];           // (qd_g) * wd2
__device__ float  g_KEYC[NBH*9*LL];         // comp-major keys: kr xyz, -wd2*kd xyz (or -1e18), v xyz
__device__ float4 g_PART[NBH*LL*2];         // partial (a0,a1,a2,sum) per key-half

// ============ kernel 1: frames + 5 projections + rotate/scale ============
// 128 threads, 16 rows per block, grid 256
__global__ void __launch_bounds__(128) k_proj(
    const float* __restrict__ x, const float* __restrict__ coords,
    const int* __restrict__ cel,
    const float* __restrict__ W0, const float* __restrict__ b0,
    const float* __restrict__ W1, const float* __restrict__ b1,
    const float* __restrict__ W2, const float* __restrict__ b2,
    const float* __restrict__ W3, const float* __restrict__ b3,
    const float* __restrict__ W4, const float* __restrict__ b4,
    const int* __restrict__ mask,
    const float* __restrict__ w_r, const float* __restrict__ w_d)
{
    __shared__ __align__(16) float2 xsp[512][8];   // 32 KB: [dim][row-pair] = (row 2rp, row 2rp+1)
    __shared__ __align__(16) float  sres[16*120];  // 7.5 KB
    __shared__ float sRt[16*12];
    __shared__ float sW[2][HH];

    int tid  = threadIdx.x;
    int row0 = blockIdx.x * 16;

    // ---- frames for this block's 16 rows (threads 0..15) ----
    if (tid < 16) {
        int gl = row0 + tid;
        const float* cp = coords + gl * 9;
        float nx=cp[0], ny=cp[1], nz=cp[2];
        float cax=cp[3], cay=cp[4], caz=cp[5];
        float cx=cp[6], cy=cp[7], cz=cp[8];
        float xx=cax-cx, xy=cay-cy, xz=caz-cz;
        float inv = 1.f / fmaxf(sqrtf(xx*xx + xy*xy + xz*xz), 1e-8f);
        xx*=inv; xy*=inv; xz*=inv;
        float yx=nx-cax, yy=ny-cay, yz=nz-caz;
        float d = xx*yx + xy*yy + xz*yz;
        yx -= d*xx; yy -= d*xy; yz -= d*xz;
        inv = 1.f / fmaxf(sqrtf(yx*yx + yy*yy + yz*yz), 1e-8f);
        yx*=inv; yy*=inv; yz*=inv;
        float zx = xy*yz - xz*yy;
        float zy = xz*yx - xx*yz;
        float zz = xx*yy - xy*yx;
        inv = 1.f / fmaxf(sqrtf(zx*zx + zy*zy + zz*zz), 1e-8f);
        zx*=inv; zy*=inv; zz*=inv;
        float R[12];
        if (cel[gl] != 0) {
            R[0]=xx; R[1]=xy; R[2]=xz; R[3]=yx; R[4]=yy; R[5]=yz;
            R[6]=zx; R[7]=zy; R[8]=zz; R[9]=cax; R[10]=cay; R[11]=caz;
        } else {
            R[0]=1.f;R[1]=0.f;R[2]=0.f; R[3]=0.f;R[4]=1.f;R[5]=0.f;
            R[6]=0.f;R[7]=0.f;R[8]=1.f; R[9]=0.f;R[10]=0.f;R[11]=0.f;
        }
        #pragma unroll
        for (int i=0;i<12;i++) { sRt[tid*12+i] = R[i]; g_Rt[gl*12+i] = R[i]; }
    } else if (tid < 24) {
        int h = tid - 16;
        const float C = 1.44269504088896f * 0.57735026918962f;  // log2e/sqrt3
        sW[0][h] = log1pf(__expf(w_r[h])) * C;
        sW[1][h] = log1pf(__expf(w_d[h])) * C;
    }

    // ---- stage x into row-pair-packed smem ----
    {
        int rp = tid & 7, q = tid >> 3;      // q in [0,16): 32-dim chunk
        const float* rA = x + (size_t)(row0 + 2*rp    )*512 + q*32;
        const float* rB = x + (size_t)(row0 + 2*rp + 1)*512 + q*32;
        #pragma unroll
        for (int i=0;i<32;i+=4) {
            float4 a = *(const float4*)(rA + i);
            float4 b = *(const float4*)(rB + i);
            xsp[q*32+i+0][rp] = make_float2(a.x, b.x);
            xsp[q*32+i+1][rp] = make_float2(a.y, b.y);
            xsp[q*32+i+2][rp] = make_float2(a.z, b.z);
            xsp[q*32+i+3][rp] = make_float2(a.w, b.w);
        }
    }
    __syncthreads();

    // ---- GEMM: 120 threads, one fused-output column each, f32x2 over row pairs ----
    if (tid < 120) {
        int m = tid / 24, c = tid % 24;
        const float* W; const float* bv;
        switch (m) {
            case 0:  W=W0; bv=b0; break;
            case 1:  W=W1; bv=b1; break;
            case 2:  W=W2; bv=b2; break;
            case 3:  W=W3; bv=b3; break;
            default: W=W4; bv=b4; break;
        }
        float bias = bv[c];
        u64 bias2 = pack2(bias, bias);
        u64 acc[8];
        #pragma unroll
        for (int j=0;j<8;j++) acc[j] = bias2;
        const float* Wc = W + c;
        const ulonglong2* X = (const ulonglong2*)xsp;
        #pragma unroll 4
        for (int dd=0; dd<512; dd++) {
            float w = __ldg(Wc + dd*24);
            u64 w2 = pack2(w, w);
            ulonglong2 x0 = X[dd*4+0];
            ulonglong2 x1 = X[dd*4+1];
            ulonglong2 x2 = X[dd*4+2];
            ulonglong2 x3 = X[dd*4+3];
            acc[0] = fma2(x0.x, w2, acc[0]);
            acc[1] = fma2(x0.y, w2, acc[1]);
            acc[2] = fma2(x1.x, w2, acc[2]);
            acc[3] = fma2(x1.y, w2, acc[3]);
            acc[4] = fma2(x2.x, w2, acc[4]);
            acc[5] = fma2(x2.y, w2, acc[5]);
            acc[6] = fma2(x3.x, w2, acc[6]);
            acc[7] = fma2(x3.y, w2, acc[7]);
        }
        #pragma unroll
        for (int j=0;j<8;j++) {
            float2 v = unpack2(acc[j]);
            sres[(2*j  )*120 + tid] = v.x;
            sres[(2*j+1)*120 + tid] = v.y;
        }
    }
    __syncthreads();

    // ---- rotate + scale + store ----
    {
        int r = tid >> 3, h = tid & 7;
        int gl = row0 + r;
        float Rm[12];
        #pragma unroll
        for (int i=0;i<12;i++) Rm[i] = sRt[r*12+i];
        const float* rowv = &sres[r*120];
        int base = h*3;

        float qr0=rowv[ 0+base], qr1=rowv[ 1+base], qr2=rowv[ 2+base];
        float kr0=rowv[24+base], kr1=rowv[25+base], kr2=rowv[26+base];
        float qd0=rowv[48+base], qd1=rowv[49+base], qd2=rowv[50+base];
        float kd0=rowv[72+base], kd1=rowv[73+base], kd2=rowv[74+base];
        float vv0=rowv[96+base], vv1=rowv[97+base], vv2=rowv[98+base];

        #define ROT3(o0,o1,o2,a0,a1,a2)                          \
            o0 = a0*Rm[0] + a1*Rm[3] + a2*Rm[6];                 \
            o1 = a0*Rm[1] + a1*Rm[4] + a2*Rm[7];                 \
            o2 = a0*Rm[2] + a1*Rm[5] + a2*Rm[8];
        float qrg0,qrg1,qrg2, krg0,krg1,krg2, qdg0,qdg1,qdg2, kdg0,kdg1,kdg2, vg0,vg1,vg2;
        ROT3(qrg0,qrg1,qrg2, qr0,qr1,qr2);
        ROT3(krg0,krg1,krg2, kr0,kr1,kr2);
        ROT3(qdg0,qdg1,qdg2, qd0,qd1,qd2);
        ROT3(kdg0,kdg1,kdg2, kd0,kd1,kd2);
        ROT3(vg0, vg1, vg2,  vv0,vv1,vv2);
        #undef ROT3

        float wr2 = sW[0][h], wd2 = sW[1][h];
        qdg0 = (qdg0 + Rm[9]) * wd2; qdg1 = (qdg1 + Rm[10]) * wd2; qdg2 = (qdg2 + Rm[11]) * wd2;
        float kn0, kn1, kn2;
        if (mask[gl] == 0) { kn0 = kn1 = kn2 = -1e18f; }
        else {
            kn0 = -(kdg0 + Rm[9] ) * wd2;
            kn1 = -(kdg1 + Rm[10]) * wd2;
            kn2 = -(kdg2 + Rm[11]) * wd2;
        }
        qrg0 *= wr2; qrg1 *= wr2; qrg2 *= wr2;

        int b = gl >> 10, l = gl & 1023;
        int bh = b*HH + h;
        g_QR[bh*LL + l] = make_float4(qrg0, qrg1, qrg2, 0.f);
        g_QD[bh*LL + l] = make_float4(qdg0, qdg1, qdg2, 0.f);
        float* kc = g_KEYC + (size_t)(bh*9)*LL + l;
        kc[0*LL]=krg0; kc[1*LL]=krg1; kc[2*LL]=krg2;
        kc[3*LL]=kn0;  kc[4*LL]=kn1;  kc[5*LL]=kn2;
        kc[6*LL]=vg0;  kc[7*LL]=vg1;  kc[8*LL]=vg2;
    }
}

// ============ kernel 2: attention (key-split partials, f32x2) ============
// grid 512 = bh(32) x qtile(8) x khalf(2); 128 threads = 128 queries; 512 keys in smem
__global__ void __launch_bounds__(128) k_attn()
{
    __shared__ __align__(16) float sK[9*512];   // 18 KB, comp-major
    int tid  = threadIdx.x;
    int kh   = blockIdx.x & 1;
    int tile = (blockIdx.x >> 1) & 7;
    int bh   = blockIdx.x >> 4;

    #pragma unroll
    for (int comp=0; comp<9; comp++)
        ((float4*)sK)[comp*128 + tid] =
            *(const float4*)(g_KEYC + (size_t)(bh*9 + comp)*LL + kh*512 + tid*4);
    __syncthreads();

    int i = tile*128 + tid;
    int q = bh*LL + i;
    float4 QR = g_QR[q];
    float4 QD = g_QD[q];
    u64 qrx = pack2(QR.x, QR.x), qry = pack2(QR.y, QR.y), qrz = pack2(QR.z, QR.z);
    u64 qdx = pack2(QD.x, QD.x), qdy = pack2(QD.y, QD.y), qdz = pack2(QD.z, QD.z);

    const ulonglong2* KRX = (const ulonglong2*)(sK + 0*512);
    const ulonglong2* KRY = (const ulonglong2*)(sK + 1*512);
    const ulonglong2* KRZ = (const ulonglong2*)(sK + 2*512);
    const ulonglong2* KDX = (const ulonglong2*)(sK + 3*512);
    const ulonglong2* KDY = (const ulonglong2*)(sK + 4*512);
    const ulonglong2* KDZ = (const ulonglong2*)(sK + 5*512);
    const ulonglong2* VX  = (const ulonglong2*)(sK + 6*512);
    const ulonglong2* VY  = (const ulonglong2*)(sK + 7*512);
    const ulonglong2* VZ  = (const ulonglong2*)(sK + 8*512);

    u64 sum2 = 0ull, a0 = 0ull, a1 = 0ull, a2 = 0ull;

    #pragma unroll 2
    for (int jj=0; jj<128; jj++) {
        ulonglong2 krx = KRX[jj], kry = KRY[jj], krz = KRZ[jj];
        ulonglong2 kdx = KDX[jj], kdy = KDY[jj], kdz = KDZ[jj];
        ulonglong2 vx  = VX[jj],  vy  = VY[jj],  vz  = VZ[jj];
        // keys 4jj, 4jj+1
        {
            u64 dir = fma2(qrz, krz.x, fma2(qry, kry.x, mul2(qrx, krx.x)));
            u64 dx = add2(qdx, kdx.x);
            u64 dy = add2(qdy, kdy.x);
            u64 dz = add2(qdz, kdz.x);
            u64 d2 = fma2(dz, dz, fma2(dy, dy, mul2(dx, dx)));
            float2 d2f = unpack2(d2);
            float2 dirf = unpack2(dir);
            float p0 = ex2_approx(dirf.x - sqrt_approx(d2f.x));
            float p1 = ex2_approx(dirf.y - sqrt_approx(d2f.y));
            u64 p = pack2(p0, p1);
            sum2 = add2(sum2, p);
            a0 = fma2(p, vx.x, a0);
            a1 = fma2(p, vy.x, a1);
            a2 = fma2(p, vz.x, a2);
        }
        // keys 4jj+2, 4jj+3
        {
            u64 dir = fma2(qrz, krz.y, fma2(qry, kry.y, mul2(qrx, krx.y)));
            u64 dx = add2(qdx, kdx.y);
            u64 dy = add2(qdy, kdy.y);
            u64 dz = add2(qdz, kdz.y);
            u64 d2 = fma2(dz, dz, fma2(dy, dy, mul2(dx, dx)));
            float2 d2f = unpack2(d2);
            float2 dirf = unpack2(dir);
            float p0 = ex2_approx(dirf.x - sqrt_approx(d2f.x));
            float p1 = ex2_approx(dirf.y - sqrt_approx(d2f.y));
            u64 p = pack2(p0, p1);
            sum2 = add2(sum2, p);
            a0 = fma2(p, vx.y, a0);
            a1 = fma2(p, vy.y, a1);
            a2 = fma2(p, vz.y, a2);
        }
    }
    float2 s = unpack2(sum2), A0 = unpack2(a0), A1 = unpack2(a1), A2 = unpack2(a2);
    g_PART[q*2 + kh] = make_float4(A0.x+A0.y, A1.x+A1.y, A2.x+A2.y, s.x+s.y);
}

// ============ kernel 3: combine + back-rotate + output projection ============
// 256 threads, 16 rows per block, grid 256
__global__ void __launch_bounds__(256) k_out(
    const float* __restrict__ Wp, const float* __restrict__ bp,
    const int* __restrict__ mask, float* __restrict__ out)
{
    __shared__ __align__(16) float so[16*24];
    __shared__ float smask[16];
    int tid = threadIdx.x;
    int gl0 = blockIdx.x * 16;

    if (tid < 128) {
        int r = tid >> 3, h = tid & 7;
        int gl = gl0 + r;
        int b = gl >> 10, l = gl & 1023;
        int q = (b*HH + h)*LL + l;
        float4 pa = g_PART[q*2 + 0];
        float4 pb = g_PART[q*2 + 1];
        float inv = 1.f / (pa.w + pb.w);
        float o0 = (pa.x + pb.x) * inv;
        float o1 = (pa.y + pb.y) * inv;
        float o2 = (pa.z + pb.z) * inv;
        float Rm[9];
        #pragma unroll
        for (int i=0;i<9;i++) Rm[i] = g_Rt[gl*12 + i];
        so[r*24 + h*3 + 0] = o0*Rm[0] + o1*Rm[3] + o2*Rm[6];
        so[r*24 + h*3 + 1] = o0*Rm[1] + o1*Rm[4] + o2*Rm[7];
        so[r*24 + h*3 + 2] = o0*Rm[2] + o1*Rm[5] + o2*Rm[8];
        if (h == 0) smask[r] = (mask[gl] != 0) ? 1.f : 0.f;
    }
    __syncthreads();

    // 256 threads x 2 cols each = 512 cols; feature pairs packed
    int c0 = tid, c1 = tid + 256;
    u64 w2a[12], w2b[12];
    #pragma unroll
    for (int fp=0; fp<12; fp++) {
        w2a[fp] = pack2(__ldg(Wp + (2*fp)*512 + c0), __ldg(Wp + (2*fp+1)*512 + c0));
        w2b[fp] = pack2(__ldg(Wp + (2*fp)*512 + c1), __ldg(Wp + (2*fp+1)*512 + c1));
    }
    float ba = __ldg(bp + c0), bbb = __ldg(bp + c1);

    for (int r=0; r<16; r++) {
        const u64* o2 = (const u64*)(so + r*24);
        u64 aa = 0ull, ab = 0ull;
        #pragma unroll
        for (int fp=0; fp<12; fp++) {
            u64 ov = o2[fp];
            aa = fma2(ov, w2a[fp], aa);
            ab = fma2(ov, w2b[fp], ab);
        }
        float2 fa = unpack2(aa), fb = unpack2(ab);
        float mf = smask[r];
        int gl = gl0 + r;
        out[(size_t)gl*512 + c0] = (fa.x + fa.y + ba ) * mf;
        out[(size_t)gl*512 + c1] = (fb.x + fb.y + bbb) * mf;
    }
}

// ================= launch =================
extern "C" void kernel_launch(void* const* d_in, const int* in_sizes, int n_in,
                              void* d_out, int out_size)
{
    const float* x      = (const float*)d_in[0];
    const float* coords = (const float*)d_in[1];
    const int* cel  = (const int*)d_in[2];
    const int* mask = (const int*)d_in[3];
    const float* Wqr = (const float*)d_in[4];  const float* bqr = (const float*)d_in[5];
    const float* Wkr = (const float*)d_in[6];  const float* bkr = (const float*)d_in[7];
    const float* Wqd = (const float*)d_in[8];  const float* bqd = (const float*)d_in[9];
    const float* Wkd = (const float*)d_in[10]; const float* bkd = (const float*)d_in[11];
    const float* Wv  = (const float*)d_in[12]; const float* bv  = (const float*)d_in[13];
    const float* w_r = (const float*)d_in[14]; const float* w_d = (const float*)d_in[15];
    const float* Wp  = (const float*)d_in[16]; const float* bp  = (const float*)d_in[17];

    k_proj<<<BL/16, 128>>>(x, coords, cel,
                           Wqr,bqr, Wkr,bkr, Wqd,bqd, Wkd,bkd, Wv,bv,
                           mask, w_r, w_d);
    k_attn<<<NBH*8*2, 128>>>();
    k_out <<<BL/16, 256>>>(Wp, bp, mask, (float*)d_out);
}